// round 16
// baseline (speedup 1.0000x reference)
#include <cuda_runtime.h>
#include <cuda_bf16.h>
#include <cstdint>

#define BB 8
#define SS 4096           // WIDTH*WIDTH
#define EE 128
#define WIDTH 64
#define NEDGE 512         // 32 paths * 16 edges per batch
#define MAXL 32           // cap on same-src edge list
#define UU 4              // edges per fused block
#define FILL_BLOCKS 2048  // 16 MB attn fill: 2048 blocks x 512 thr x 16 B

// Combined weights: Wc = Wv @ Wp, bc = bv @ Wp
__device__ float g_Wc[EE * EE];
__device__ float g_bc[EE];

// ---------------------------------------------------------------------------
// prep_fill: blocks [0,128)   -> Wc row i via split-K (4 chunks x 32 k-steps)
//            blocks [128, +FILL_BLOCKS) -> bp broadcast fill of attn region
__global__ __launch_bounds__(512)
void prep_fill_kernel(const float* __restrict__ Wv,
                      const float* __restrict__ Wp,
                      const float* __restrict__ bv,
                      float4* __restrict__ attn4,
                      const float4* __restrict__ bp4) {
    int t = threadIdx.x;
    if (blockIdx.x < EE) {
        // ---- combine: row i of Wc ----
        int i  = blockIdx.x;
        int j  = t & 127;
        int kc = t >> 7;                  // 0..3
        __shared__ float part[4][EE];
        __shared__ float wvrow[EE];
        if (kc == 0) wvrow[j] = Wv[i * EE + j];
        __syncthreads();

        float acc = 0.0f;
        int k0 = kc * 32;
        #pragma unroll
        for (int k = 0; k < 32; k++)
            acc = fmaf(wvrow[k0 + k], Wp[(k0 + k) * EE + j], acc);
        part[kc][j] = acc;
        __syncthreads();
        if (kc == 0) {
            g_Wc[i * EE + j] = (part[0][j] + part[1][j]) + (part[2][j] + part[3][j]);
        } else if (i == 0 && kc == 1) {
            float b = 0.0f;
            #pragma unroll 16
            for (int k = 0; k < EE; k++)
                b = fmaf(bv[k], Wp[k * EE + j], b);
            g_bc[j] = b;
        }
    } else {
        // ---- bp broadcast fill: 512 float4s per block ----
        unsigned idx = (blockIdx.x - EE) * 512u + t;
        attn4[idx] = bp4[t & 31];
    }
}

// ---------------------------------------------------------------------------
// Fused output + adjacency ones: one block per UU=4 edges (1024 x 128).
// Per sub-edge: write A1/A2 ones (idempotent); if first-src edge, gather
// same-src dsts, dedupe by value, sum value rows, shared-weight matvec.
__global__ __launch_bounds__(128)
void fused_out_kernel(float* __restrict__ attn,
                      float* __restrict__ A1,
                      float* __restrict__ A2,
                      const float* __restrict__ values,
                      const float* __restrict__ bp,
                      const int* __restrict__ edges) {
    __shared__ int ssrc[NEDGE];
    __shared__ int sdst[NEDGE];
    __shared__ int list[UU][MAXL];
    __shared__ int nlist[UU];
    __shared__ int dupflag[UU];
    __shared__ float accv[UU][EE];

    int b = blockIdx.y;
    int i0 = blockIdx.x * UU;             // edges i0 .. i0+UU-1
    int e = threadIdx.x;

    const int4* eg = (const int4*)(edges + (size_t)b * NEDGE * 4);
    #pragma unroll
    for (int q = 0; q < 4; q++) {
        int t = e + q * EE;
        int4 v = eg[t];
        ssrc[t] = v.y * WIDTH + v.x;
        sdst[t] = v.w * WIDTH + v.z;
    }
    if (e < UU) { nlist[e] = 0; dupflag[e] = 0; }
    __syncthreads();

    // adjacency ones (after memset in stream order; idempotent)
    if (e < UU) {
        int i = i0 + e;
        size_t off = ((size_t)b * SS + ssrc[i]) * SS + sdst[i];
        A1[off] = 1.0f;
        A2[off] = 1.0f;
    }

    int my[UU];
    #pragma unroll
    for (int r = 0; r < UU; r++) my[r] = ssrc[i0 + r];

    // first-src check + same-src dst collection (4 smem reads/thread)
    #pragma unroll
    for (int q = 0; q < 4; q++) {
        int t = e + q * EE;
        int s = ssrc[t];
        #pragma unroll
        for (int r = 0; r < UU; r++) {
            if (s == my[r]) {
                if (t < i0 + r) dupflag[r] = 1;
                int p = atomicAdd(&nlist[r], 1);
                if (p < MAXL) list[r][p] = sdst[t];
            }
        }
    }
    __syncthreads();

    int d[UU];
    int alldup = 1;
    #pragma unroll
    for (int r = 0; r < UU; r++) { d[r] = dupflag[r]; alldup &= d[r]; }
    if (alldup) return;

    // unique-by-value sums (order-independent => deterministic)
    int m[UU];
    #pragma unroll
    for (int r = 0; r < UU; r++) {
        float acc = 0.0f;
        m[r] = 0;
        if (!d[r]) {
            int n = nlist[r] < MAXL ? nlist[r] : MAXL;
            for (int q = 0; q < n; q++) {
                int dd = list[r][q];
                bool uniq = true;
                for (int p = 0; p < q; p++)
                    if (list[r][p] == dd) { uniq = false; break; }
                if (uniq) {
                    acc += values[((size_t)b * SS + dd) * EE + e];
                    m[r]++;
                }
            }
        }
        accv[r][e] = acc;
    }
    __syncthreads();

    // shared-weight matvec: each Wc element feeds UU rows
    float bce = g_bc[e], bpe = bp[e];
    float o[UU];
    #pragma unroll
    for (int r = 0; r < UU; r++) o[r] = fmaf((float)m[r], bce, bpe);

    #pragma unroll 8
    for (int k = 0; k < EE; k++) {
        float w = g_Wc[k * EE + e];
        #pragma unroll
        for (int r = 0; r < UU; r++)
            o[r] = fmaf(accv[r][k], w, o[r]);
    }

    #pragma unroll
    for (int r = 0; r < UU; r++)
        if (!d[r]) attn[((size_t)b * SS + my[r]) * EE + e] = o[r];
}

// ---------------------------------------------------------------------------
extern "C" void kernel_launch(void* const* d_in, const int* in_sizes, int n_in,
                              void* d_out, int out_size) {
    (void)in_sizes; (void)n_in; (void)out_size;

    const float* values = (const float*)d_in[2];
    const int*   edges  = (const int*)  d_in[3];
    const float* Wv     = (const float*)d_in[8];
    const float* bv     = (const float*)d_in[9];
    const float* Wp     = (const float*)d_in[10];
    const float* bp     = (const float*)d_in[11];

    float* out  = (float*)d_out;
    float* attn = out;                                    // [B,S,E]
    float* A1   = out + (size_t)BB * SS * EE;             // [B,S,S]
    float* A2   = A1 + (size_t)BB * SS * SS;              // [B,S,S]

    // 1) bulk zeros via memset (fastest store path, ~147 us)
    cudaMemsetAsync(A1, 0, 2ull * BB * SS * SS * sizeof(float));

    // 2) combined weights + bp broadcast fill, one launch (~4 us)
    prep_fill_kernel<<<EE + FILL_BLOCKS, 512>>>(Wv, Wp, bv,
                                                (float4*)attn, (const float4*)bp);

    // 3) fused sparse output + adjacency ones (~10-12 us, 1024 blocks)
    {
        dim3 grid(NEDGE / UU, BB);
        fused_out_kernel<<<grid, EE>>>(attn, A1, A2, values, bp, edges);
    }
}